// round 1
// baseline (speedup 1.0000x reference)
#include <cuda_runtime.h>

#define NN 50000
#define EE 800000
#define IND 64
#define HH 4
#define DD 16
#define HD 64              // H*D
#define NB_SCAN 49         // ceil(NN/1024)

// ---------------- scratch (device globals; no allocation allowed) ----------------
__device__ float g_Q[NN * HD];
__device__ float g_K[NN * HD];
__device__ float g_V[NN * HD];
__device__ int   g_deg[NN];
__device__ int   g_cursor[NN];
__device__ int   g_start[NN + 1];
__device__ int   g_esrc[EE];
__device__ int   g_bsum[64];

// ---------------- zero counters ----------------
__global__ void zero_kernel() {
    int i = blockIdx.x * blockDim.x + threadIdx.x;
    if (i < NN) { g_deg[i] = 0; g_cursor[i] = 0; }
}

// ---------------- fused QKV GEMM: [N,64] x [64,64] (+bias), x3 ----------------
// Block: 256 threads, 64 nodes. Thread t: c4 = t&15 (4 cols), ng = t>>4 (4 nodes).
// Register tile 4 nodes x 4 cols -> 64 FMA per 8 LDS.128 (FMA-bound).
__global__ void __launch_bounds__(256) qkv_kernel(
    const float* __restrict__ h,
    const float* __restrict__ Wq, const float* __restrict__ bq,
    const float* __restrict__ Wk, const float* __restrict__ bk,
    const float* __restrict__ Wv, const float* __restrict__ bv)
{
    __shared__ float4 hs[64][16];   // 64 nodes x 64 floats (16KB)
    __shared__ float4 Ws[64][16];   // 64x64 W (16KB)
    __shared__ float4 bs[16];

    int t  = threadIdx.x;
    int n0 = blockIdx.x * 64;

    for (int i = t; i < 64 * 16; i += 256) {
        int n = i >> 4, k4 = i & 15;
        int gn = n0 + n; if (gn >= NN) gn = NN - 1;   // clamp (tail) — writes are guarded
        hs[n][k4] = ((const float4*)h)[gn * 16 + k4];
    }

    int c4 = t & 15;
    int ng = t >> 4;

    for (int m = 0; m < 3; m++) {
        const float* Wm = (m == 0) ? Wq : ((m == 1) ? Wk : Wv);
        const float* bm = (m == 0) ? bq : ((m == 1) ? bk : bv);
        float*       Om = (m == 0) ? g_Q : ((m == 1) ? g_K : g_V);

        __syncthreads();   // hs ready / previous Ws reads done
        for (int i = t; i < 64 * 16; i += 256) Ws[i >> 4][i & 15] = ((const float4*)Wm)[i];
        if (t < 16) bs[t] = ((const float4*)bm)[t];
        __syncthreads();

        float4 acc0 = bs[c4], acc1 = bs[c4], acc2 = bs[c4], acc3 = bs[c4];

        #pragma unroll
        for (int kq = 0; kq < 16; kq++) {
            float4 w0 = Ws[kq * 4 + 0][c4];
            float4 w1 = Ws[kq * 4 + 1][c4];
            float4 w2 = Ws[kq * 4 + 2][c4];
            float4 w3 = Ws[kq * 4 + 3][c4];
            float4 hv;
            #define ACC16(A, NI)                                                     \
                hv = hs[ng * 4 + NI][kq];                                            \
                A.x = fmaf(hv.x, w0.x, A.x); A.y = fmaf(hv.x, w0.y, A.y);            \
                A.z = fmaf(hv.x, w0.z, A.z); A.w = fmaf(hv.x, w0.w, A.w);            \
                A.x = fmaf(hv.y, w1.x, A.x); A.y = fmaf(hv.y, w1.y, A.y);            \
                A.z = fmaf(hv.y, w1.z, A.z); A.w = fmaf(hv.y, w1.w, A.w);            \
                A.x = fmaf(hv.z, w2.x, A.x); A.y = fmaf(hv.z, w2.y, A.y);            \
                A.z = fmaf(hv.z, w2.z, A.z); A.w = fmaf(hv.z, w2.w, A.w);            \
                A.x = fmaf(hv.w, w3.x, A.x); A.y = fmaf(hv.w, w3.y, A.y);            \
                A.z = fmaf(hv.w, w3.z, A.z); A.w = fmaf(hv.w, w3.w, A.w);
            ACC16(acc0, 0) ACC16(acc1, 1) ACC16(acc2, 2) ACC16(acc3, 3)
            #undef ACC16
        }

        int gn = n0 + ng * 4;
        if (gn + 0 < NN) ((float4*)Om)[(gn + 0) * 16 + c4] = acc0;
        if (gn + 1 < NN) ((float4*)Om)[(gn + 1) * 16 + c4] = acc1;
        if (gn + 2 < NN) ((float4*)Om)[(gn + 2) * 16 + c4] = acc2;
        if (gn + 3 < NN) ((float4*)Om)[(gn + 3) * 16 + c4] = acc3;
    }
}

// ---------------- CSR build: histogram, 3-pass scan, scatter ----------------
__global__ void hist_kernel(const int* __restrict__ dst) {
    int e = blockIdx.x * blockDim.x + threadIdx.x;
    if (e < EE) atomicAdd(&g_deg[dst[e]], 1);
}

__global__ void __launch_bounds__(1024) scan1_kernel() {
    int t = threadIdx.x, b = blockIdx.x;
    int i = b * 1024 + t;
    int v = (i < NN) ? g_deg[i] : 0;
    int lane = t & 31, wid = t >> 5;
    int x = v;
    #pragma unroll
    for (int o = 1; o < 32; o <<= 1) {
        int y = __shfl_up_sync(0xffffffffu, x, o);
        if (lane >= o) x += y;
    }
    __shared__ int wsum[32];
    if (lane == 31) wsum[wid] = x;
    __syncthreads();
    if (wid == 0) {
        int y = wsum[lane];
        #pragma unroll
        for (int o = 1; o < 32; o <<= 1) {
            int z2 = __shfl_up_sync(0xffffffffu, y, o);
            if (lane >= o) y += z2;
        }
        wsum[lane] = y;
    }
    __syncthreads();
    int off  = (wid > 0) ? wsum[wid - 1] : 0;
    int incl = x + off;
    if (i < NN) g_start[i] = incl - v;        // exclusive within block
    if (t == 1023) g_bsum[b] = incl;          // block total
}

__global__ void scan2_kernel() {   // 64 threads: exclusive scan of 49 block sums
    int t = threadIdx.x;
    int v = (t < NB_SCAN) ? g_bsum[t] : 0;
    int lane = t & 31, wid = t >> 5;
    int x = v;
    #pragma unroll
    for (int o = 1; o < 32; o <<= 1) {
        int y = __shfl_up_sync(0xffffffffu, x, o);
        if (lane >= o) x += y;
    }
    __shared__ int ws[2];
    if (lane == 31) ws[wid] = x;
    __syncthreads();
    int off  = (wid == 1) ? ws[0] : 0;
    int incl = x + off;
    if (t < NB_SCAN) g_bsum[t] = incl - v;    // exclusive block offsets
}

__global__ void scan3_kernel() {
    int i = blockIdx.x * blockDim.x + threadIdx.x;
    if (i < NN) g_start[i] += g_bsum[i >> 10];
    if (i == 0) g_start[NN] = EE;
}

__global__ void scatter_kernel(const int* __restrict__ src, const int* __restrict__ dst) {
    int e = blockIdx.x * blockDim.x + threadIdx.x;
    if (e < EE) {
        int d   = dst[e];
        int pos = g_start[d] + atomicAdd(&g_cursor[d], 1);
        g_esrc[pos] = src[e];
    }
}

// ---------------- edge aggregation: one thread per (node, head) ----------------
__global__ void __launch_bounds__(256) attn_kernel(
    const float* __restrict__ s_l, float* __restrict__ out)
{
    int gid = blockIdx.x * 256 + threadIdx.x;
    if (gid >= NN * HH) return;
    int n  = gid >> 2;
    int hh = gid & 3;

    const float4* Qp = ((const float4*)g_Q) + n * 16 + hh * 4;
    float4 q0 = Qp[0], q1 = Qp[1], q2 = Qp[2], q3 = Qp[3];

    int sb = n * (HH * 3) + hh * 3;
    float sx = __ldg(s_l + sb + 0);
    float sy = __ldg(s_l + sb + 1);
    float sz = __ldg(s_l + sb + 2);

    float4 a0 = make_float4(0.f, 0.f, 0.f, 0.f);
    float4 a1 = a0, a2 = a0, a3 = a0;
    float  z  = 0.f;

    int beg = g_start[n], end = g_start[n + 1];
    for (int j = beg; j < end; j++) {
        int s = g_esrc[j];

        const float4* Kp = ((const float4*)g_K) + s * 16 + hh * 4;
        float4 k0 = Kp[0], k1 = Kp[1], k2 = Kp[2], k3 = Kp[3];
        float dot = q0.x * k0.x;
        dot = fmaf(q0.y, k0.y, dot); dot = fmaf(q0.z, k0.z, dot); dot = fmaf(q0.w, k0.w, dot);
        dot = fmaf(q1.x, k1.x, dot); dot = fmaf(q1.y, k1.y, dot); dot = fmaf(q1.z, k1.z, dot); dot = fmaf(q1.w, k1.w, dot);
        dot = fmaf(q2.x, k2.x, dot); dot = fmaf(q2.y, k2.y, dot); dot = fmaf(q2.z, k2.z, dot); dot = fmaf(q2.w, k2.w, dot);
        dot = fmaf(q3.x, k3.x, dot); dot = fmaf(q3.y, k3.y, dot); dot = fmaf(q3.z, k3.z, dot); dot = fmaf(q3.w, k3.w, dot);

        float arg = fminf(fmaxf(dot * 0.25f, -5.f), 5.f);   // scale = sqrt(16) = 4
        float sc  = __expf(arg);

        int so = s * (HH * 3) + hh * 3;
        float dx = __ldg(s_l + so + 0) - sx;
        float dy = __ldg(s_l + so + 1) - sy;
        float dz = __ldg(s_l + so + 2) - sz;
        float dij = fmaf(dx, dx, fmaf(dy, dy, dz * dz));
        float w   = __expf(-dij * dij);
        float news = sc * w;

        const float4* Vp = ((const float4*)g_V) + s * 16 + hh * 4;
        float4 v0 = Vp[0], v1 = Vp[1], v2 = Vp[2], v3 = Vp[3];
        a0.x = fmaf(v0.x, news, a0.x); a0.y = fmaf(v0.y, news, a0.y);
        a0.z = fmaf(v0.z, news, a0.z); a0.w = fmaf(v0.w, news, a0.w);
        a1.x = fmaf(v1.x, news, a1.x); a1.y = fmaf(v1.y, news, a1.y);
        a1.z = fmaf(v1.z, news, a1.z); a1.w = fmaf(v1.w, news, a1.w);
        a2.x = fmaf(v2.x, news, a2.x); a2.y = fmaf(v2.y, news, a2.y);
        a2.z = fmaf(v2.z, news, a2.z); a2.w = fmaf(v2.w, news, a2.w);
        a3.x = fmaf(v3.x, news, a3.x); a3.y = fmaf(v3.y, news, a3.y);
        a3.z = fmaf(v3.z, news, a3.z); a3.w = fmaf(v3.w, news, a3.w);

        z += sc;
    }

    float inv = (z > 0.f) ? (1.f / z) : 1.f;   // degree-0 nodes: a* = 0, write 0
    float4* Op = ((float4*)out) + n * 16 + hh * 4;
    Op[0] = make_float4(a0.x * inv, a0.y * inv, a0.z * inv, a0.w * inv);
    Op[1] = make_float4(a1.x * inv, a1.y * inv, a1.z * inv, a1.w * inv);
    Op[2] = make_float4(a2.x * inv, a2.y * inv, a2.z * inv, a2.w * inv);
    Op[3] = make_float4(a3.x * inv, a3.y * inv, a3.z * inv, a3.w * inv);
}

// ---------------- launch ----------------
extern "C" void kernel_launch(void* const* d_in, const int* in_sizes, int n_in,
                              void* d_out, int out_size)
{
    const float* h   = (const float*)d_in[0];
    const float* s_l = (const float*)d_in[1];
    const float* Wq  = (const float*)d_in[2];
    const float* bq  = (const float*)d_in[3];
    const float* Wk  = (const float*)d_in[4];
    const float* bk  = (const float*)d_in[5];
    const float* Wv  = (const float*)d_in[6];
    const float* bv  = (const float*)d_in[7];
    const int*   src = (const int*)d_in[8];
    const int*   dst = (const int*)d_in[9];
    float*       out = (float*)d_out;

    zero_kernel<<<(NN + 255) / 256, 256>>>();
    qkv_kernel<<<(NN + 63) / 64, 256>>>(h, Wq, bq, Wk, bk, Wv, bv);
    hist_kernel<<<(EE + 255) / 256, 256>>>(dst);
    scan1_kernel<<<NB_SCAN, 1024>>>();
    scan2_kernel<<<1, 64>>>();
    scan3_kernel<<<(NN + 255) / 256, 256>>>();
    scatter_kernel<<<(EE + 255) / 256, 256>>>(src, dst);
    attn_kernel<<<(NN * HH + 255) / 256, 256>>>(s_l, out);
}